// round 1
// baseline (speedup 1.0000x reference)
#include <cuda_runtime.h>
#include <math.h>
#include <stdint.h>

#define N_NODES 100000
#define N_EDGES 1600000
#define F_IN    256
#define HIDDEN  64
#define N_CLASS 2

// ---------------- scratch (static __device__; no allocation at runtime) ----
__device__ float d_hbuf[N_NODES * HIDDEN];   // GEMM output
__device__ float d_abuf[N_NODES * HIDDEN];   // aggregated output
__device__ float d_h3[N_NODES * N_CLASS];    // layer-3 GEMM output
__device__ float d_dinv[N_NODES];            // deg^{-1/2}
__device__ int   d_cnt[N_NODES];             // incoming-edge count (no self loop)
__device__ int   d_fill[N_NODES];            // fill cursor per node
__device__ int   d_rowstart[N_NODES];        // CSR row start
__device__ int   d_csr_src[N_EDGES];         // CSR: src node per incoming edge
__device__ int   d_cursor;

// ---------------- CSR build ------------------------------------------------
__global__ void k_init() {
    int i = blockIdx.x * blockDim.x + threadIdx.x;
    if (i < N_NODES) { d_cnt[i] = 0; d_fill[i] = 0; }
    if (i == 0) d_cursor = 0;
}

__global__ void k_count(const int* __restrict__ dst) {
    int e = blockIdx.x * blockDim.x + threadIdx.x;
    if (e < N_EDGES) atomicAdd(&d_cnt[dst[e]], 1);
}

__global__ void k_node() {
    int i = blockIdx.x * blockDim.x + threadIdx.x;
    if (i < N_NODES) {
        int c = d_cnt[i];
        d_dinv[i] = rsqrtf((float)(c + 1));           // +1 self loop; deg>=1
        d_rowstart[i] = atomicAdd(&d_cursor, c);
    }
}

__global__ void k_fill(const int* __restrict__ src, const int* __restrict__ dst) {
    int e = blockIdx.x * blockDim.x + threadIdx.x;
    if (e < N_EDGES) {
        int d = dst[e];
        int pos = d_rowstart[d] + atomicAdd(&d_fill[d], 1);
        d_csr_src[pos] = src[e];
    }
}

// ---------------- GEMM: C[M,64] = A[M,K] @ W[K,64] -------------------------
// 64x64 block tile, BK=32, 256 threads, 4x4 register micro-tile per thread.
template <int K>
__global__ void k_gemm64(const float* __restrict__ A, const float* __restrict__ W,
                         float* __restrict__ C) {
    __shared__ float xs[64][33];   // padded: conflict-free column reads
    __shared__ float ws[32][64];
    const int m0  = blockIdx.x * 64;
    const int tid = threadIdx.x;
    const int tx  = tid & 15;       // N direction (16)
    const int ty  = tid >> 4;       // M direction (16)

    float acc[4][4] = {};

    for (int k0 = 0; k0 < K; k0 += 32) {
        // load A tile: 64 rows x 32 k = 512 float4
        #pragma unroll
        for (int t = tid; t < 512; t += 256) {
            int r  = t >> 3;            // 8 float4 per row
            int kk = (t & 7) * 4;
            int gr = m0 + r;
            float4 v = make_float4(0.f, 0.f, 0.f, 0.f);
            if (gr < N_NODES)
                v = *(const float4*)&A[(size_t)gr * K + k0 + kk];
            xs[r][kk + 0] = v.x; xs[r][kk + 1] = v.y;
            xs[r][kk + 2] = v.z; xs[r][kk + 3] = v.w;
        }
        // load W tile: 32 rows x 64 cols = 512 float4
        #pragma unroll
        for (int t = tid; t < 512; t += 256) {
            int r  = t >> 4;            // 16 float4 per row
            int cc = (t & 15) * 4;
            float4 v = *(const float4*)&W[(size_t)(k0 + r) * 64 + cc];
            *(float4*)&ws[r][cc] = v;
        }
        __syncthreads();

        #pragma unroll
        for (int kk = 0; kk < 32; kk++) {
            float a[4], b[4];
            #pragma unroll
            for (int i = 0; i < 4; i++) a[i] = xs[ty + 16 * i][kk];
            #pragma unroll
            for (int j = 0; j < 4; j++) b[j] = ws[kk][tx + 16 * j];
            #pragma unroll
            for (int i = 0; i < 4; i++)
                #pragma unroll
                for (int j = 0; j < 4; j++)
                    acc[i][j] = fmaf(a[i], b[j], acc[i][j]);
        }
        __syncthreads();
    }

    #pragma unroll
    for (int i = 0; i < 4; i++) {
        int gr = m0 + ty + 16 * i;
        if (gr < N_NODES) {
            #pragma unroll
            for (int j = 0; j < 4; j++)
                C[(size_t)gr * 64 + tx + 16 * j] = acc[i][j];
        }
    }
}

// ---------------- aggregation (64-wide): warp per dst node ------------------
__global__ void k_agg(const float* __restrict__ h, const float* __restrict__ bias,
                      float* __restrict__ out, int relu) {
    int gwarp = (blockIdx.x * blockDim.x + threadIdx.x) >> 5;
    int lane  = threadIdx.x & 31;
    if (gwarp >= N_NODES) return;
    const int i = gwarp;

    const float di = d_dinv[i];
    const int start = d_rowstart[i];
    const int n     = d_cnt[i];

    // self loop: norm = di*di
    float a0 = h[(size_t)i * 64 + lane]      * (di * di);
    float a1 = h[(size_t)i * 64 + lane + 32] * (di * di);

    int e = 0;
    // 2x unrolled for memory-level parallelism against L2 latency
    for (; e + 1 < n; e += 2) {
        int s0 = d_csr_src[start + e];
        int s1 = d_csr_src[start + e + 1];
        float n0 = d_dinv[s0] * di;
        float n1 = d_dinv[s1] * di;
        float h00 = h[(size_t)s0 * 64 + lane];
        float h01 = h[(size_t)s0 * 64 + lane + 32];
        float h10 = h[(size_t)s1 * 64 + lane];
        float h11 = h[(size_t)s1 * 64 + lane + 32];
        a0 = fmaf(h00, n0, a0); a1 = fmaf(h01, n0, a1);
        a0 = fmaf(h10, n1, a0); a1 = fmaf(h11, n1, a1);
    }
    if (e < n) {
        int s = d_csr_src[start + e];
        float nrm = d_dinv[s] * di;
        a0 = fmaf(h[(size_t)s * 64 + lane],      nrm, a0);
        a1 = fmaf(h[(size_t)s * 64 + lane + 32], nrm, a1);
    }

    a0 += bias[lane];
    a1 += bias[lane + 32];
    if (relu) { a0 = fmaxf(a0, 0.f); a1 = fmaxf(a1, 0.f); }
    out[(size_t)i * 64 + lane]      = a0;
    out[(size_t)i * 64 + lane + 32] = a1;
}

// ---------------- layer 3 GEMM: [N,64] @ [64,2] -> [N,2] --------------------
__global__ void k_gemm3(const float* __restrict__ A, const float* __restrict__ W3,
                        float* __restrict__ H3) {
    int gwarp = (blockIdx.x * blockDim.x + threadIdx.x) >> 5;
    int lane  = threadIdx.x & 31;
    if (gwarp >= N_NODES) return;
    const int i = gwarp;

    float v0 = A[(size_t)i * 64 + lane];
    float v1 = A[(size_t)i * 64 + lane + 32];
    float p0 = v0 * W3[lane * 2 + 0] + v1 * W3[(lane + 32) * 2 + 0];
    float p1 = v0 * W3[lane * 2 + 1] + v1 * W3[(lane + 32) * 2 + 1];
    #pragma unroll
    for (int off = 16; off > 0; off >>= 1) {
        p0 += __shfl_down_sync(0xFFFFFFFFu, p0, off);
        p1 += __shfl_down_sync(0xFFFFFFFFu, p1, off);
    }
    if (lane == 0) {
        H3[(size_t)i * 2 + 0] = p0;
        H3[(size_t)i * 2 + 1] = p1;
    }
}

// ---------------- layer 3 aggregation + bias + log_softmax ------------------
__global__ void k_agg3(const float* __restrict__ h3, const float* __restrict__ b3,
                       float* __restrict__ out) {
    int gwarp = (blockIdx.x * blockDim.x + threadIdx.x) >> 5;
    int lane  = threadIdx.x & 31;
    if (gwarp >= N_NODES) return;
    const int i = gwarp;

    const float di = d_dinv[i];
    const int start = d_rowstart[i];
    const int n     = d_cnt[i];

    float a0 = 0.f, a1 = 0.f;
    for (int e = lane; e < n; e += 32) {
        int s = d_csr_src[start + e];
        float nrm = d_dinv[s] * di;
        a0 = fmaf(h3[(size_t)s * 2 + 0], nrm, a0);
        a1 = fmaf(h3[(size_t)s * 2 + 1], nrm, a1);
    }
    #pragma unroll
    for (int off = 16; off > 0; off >>= 1) {
        a0 += __shfl_down_sync(0xFFFFFFFFu, a0, off);
        a1 += __shfl_down_sync(0xFFFFFFFFu, a1, off);
    }
    if (lane == 0) {
        // self loop + bias
        a0 += h3[(size_t)i * 2 + 0] * (di * di) + b3[0];
        a1 += h3[(size_t)i * 2 + 1] * (di * di) + b3[1];
        // log_softmax over 2 classes
        float m = fmaxf(a0, a1);
        float lse = m + logf(expf(a0 - m) + expf(a1 - m));
        out[(size_t)i * 2 + 0] = a0 - lse;
        out[(size_t)i * 2 + 1] = a1 - lse;
    }
}

// ---------------- launch -----------------------------------------------------
extern "C" void kernel_launch(void* const* d_in, const int* in_sizes, int n_in,
                              void* d_out, int out_size) {
    const float* x  = (const float*)d_in[0];
    const int*   ei = (const int*)d_in[1];
    const float* W1 = (const float*)d_in[2];
    const float* b1 = (const float*)d_in[3];
    const float* W2 = (const float*)d_in[4];
    const float* b2 = (const float*)d_in[5];
    const float* W3 = (const float*)d_in[6];
    const float* b3 = (const float*)d_in[7];
    float* out = (float*)d_out;

    const int* src = ei;
    const int* dst = ei + N_EDGES;

    const int NB_N = (N_NODES + 255) / 256;
    const int NB_E = (N_EDGES + 255) / 256;
    const int NB_W = (N_NODES * 32 + 255) / 256;   // warp-per-node grids
    const int NB_M = (N_NODES + 63) / 64;          // GEMM row tiles

    // CSR build
    k_init<<<NB_N, 256>>>();
    k_count<<<NB_E, 256>>>(dst);
    k_node<<<NB_N, 256>>>();
    k_fill<<<NB_E, 256>>>(src, dst);

    // get device pointers to scratch (symbols usable directly in kernels)
    float* hbuf; cudaGetSymbolAddress((void**)&hbuf, d_hbuf);
    float* abuf; cudaGetSymbolAddress((void**)&abuf, d_abuf);
    float* h3;   cudaGetSymbolAddress((void**)&h3, d_h3);

    // layer 1
    k_gemm64<F_IN><<<NB_M, 256>>>(x, W1, hbuf);
    k_agg<<<NB_W, 256>>>(hbuf, b1, abuf, 1);
    // layer 2
    k_gemm64<HIDDEN><<<NB_M, 256>>>(abuf, W2, hbuf);
    k_agg<<<NB_W, 256>>>(hbuf, b2, abuf, 1);
    // layer 3
    k_gemm3<<<NB_W, 256>>>(abuf, W3, h3);
    k_agg3<<<NB_W, 256>>>(h3, b3, out);
}

// round 3
// speedup vs baseline: 1.4577x; 1.4577x over previous
#include <cuda_runtime.h>
#include <math.h>
#include <stdint.h>

#define N_NODES 100000
#define N_EDGES 1600000
#define F_IN    256
#define HIDDEN  64
#define N_CLASS 2

// ---------------- scratch (static __device__; 16B-aligned for vector LDG) ---
__device__ __align__(16) float d_hbuf[N_NODES * HIDDEN];    // x@W1
__device__ __align__(16) float d_hbuf2[N_NODES * HIDDEN];   // h1@W2
__device__ __align__(16) float d_h3[N_NODES * N_CLASS];     // h2@W3
__device__ float d_dinv[N_NODES];             // deg^{-1/2}
__device__ int   d_cnt[N_NODES];              // incoming-edge count (no self loop)
__device__ int   d_fill[N_NODES];             // fill cursor
__device__ int   d_rowstart[N_NODES];         // CSR row start
__device__ __align__(16) int2 d_csr[N_EDGES]; // (src, bitcast(norm)) per incoming edge
__device__ int   d_cursor;

// ---------------- CSR build -------------------------------------------------
__global__ void k_count(const int4* __restrict__ dst4) {
    int t = blockIdx.x * blockDim.x + threadIdx.x;
    if (t < N_EDGES / 4) {
        int4 d = dst4[t];
        atomicAdd(&d_cnt[d.x], 1);
        atomicAdd(&d_cnt[d.y], 1);
        atomicAdd(&d_cnt[d.z], 1);
        atomicAdd(&d_cnt[d.w], 1);
    }
}

__global__ void k_node() {
    int i = blockIdx.x * blockDim.x + threadIdx.x;
    if (i < N_NODES) {
        int c = d_cnt[i];
        d_dinv[i] = rsqrtf((float)(c + 1));          // +1 self loop
        d_rowstart[i] = atomicAdd(&d_cursor, c);
    }
}

__global__ void k_fill(const int4* __restrict__ src4, const int4* __restrict__ dst4) {
    int t = blockIdx.x * blockDim.x + threadIdx.x;
    if (t < N_EDGES / 4) {
        int4 s = src4[t];
        int4 d = dst4[t];
        #pragma unroll
        for (int c = 0; c < 4; c++) {
            int ss = (c == 0) ? s.x : (c == 1) ? s.y : (c == 2) ? s.z : s.w;
            int dd = (c == 0) ? d.x : (c == 1) ? d.y : (c == 2) ? d.z : d.w;
            int pos = d_rowstart[dd] + atomicAdd(&d_fill[dd], 1);
            float nrm = d_dinv[ss] * d_dinv[dd];
            d_csr[pos] = make_int2(ss, __float_as_int(nrm));
        }
    }
}

// ---------------- GEMM1: C[M,64] = A[M,256] @ W[256,64] ---------------------
__global__ void k_gemm64(const float* __restrict__ A, const float* __restrict__ W,
                         float* __restrict__ C) {
    __shared__ float xs[64][33];
    __shared__ float ws[32][64];
    const int m0  = blockIdx.x * 64;
    const int tid = threadIdx.x;
    const int tx  = tid & 15;
    const int ty  = tid >> 4;

    float acc[4][4] = {};

    for (int k0 = 0; k0 < F_IN; k0 += 32) {
        #pragma unroll
        for (int t = tid; t < 512; t += 256) {
            int r  = t >> 3;
            int kk = (t & 7) * 4;
            int gr = m0 + r;
            float4 v = make_float4(0.f, 0.f, 0.f, 0.f);
            if (gr < N_NODES)
                v = *(const float4*)&A[(size_t)gr * F_IN + k0 + kk];
            xs[r][kk + 0] = v.x; xs[r][kk + 1] = v.y;
            xs[r][kk + 2] = v.z; xs[r][kk + 3] = v.w;
        }
        #pragma unroll
        for (int t = tid; t < 512; t += 256) {
            int r  = t >> 4;
            int cc = (t & 15) * 4;
            *(float4*)&ws[r][cc] = *(const float4*)&W[(size_t)(k0 + r) * 64 + cc];
        }
        __syncthreads();

        #pragma unroll
        for (int kk = 0; kk < 32; kk++) {
            float a[4], b[4];
            #pragma unroll
            for (int i = 0; i < 4; i++) a[i] = xs[ty + 16 * i][kk];
            #pragma unroll
            for (int j = 0; j < 4; j++) b[j] = ws[kk][tx + 16 * j];
            #pragma unroll
            for (int i = 0; i < 4; i++)
                #pragma unroll
                for (int j = 0; j < 4; j++)
                    acc[i][j] = fmaf(a[i], b[j], acc[i][j]);
        }
        __syncthreads();
    }

    #pragma unroll
    for (int i = 0; i < 4; i++) {
        int gr = m0 + ty + 16 * i;
        if (gr < N_NODES) {
            #pragma unroll
            for (int j = 0; j < 4; j++)
                C[(size_t)gr * 64 + tx + 16 * j] = acc[i][j];
        }
    }
}

// ---------------- warp-level 64-wide aggregation core -----------------------
// Warp: two 16-lane halves, each half processes a different edge per step.
// Lane l16 of each half holds feats [l16*4 .. l16*4+3] as float4.
// After the loop, shfl_xor(16) leaves the full sum in ALL 32 lanes.
__device__ __forceinline__ float4 agg_node(const float* __restrict__ h, int i,
                                           int h5 /*0 or 1*/, int l16) {
    const float di = d_dinv[i];
    const int base = d_rowstart[i];
    const int n    = d_cnt[i];

    float4 acc = make_float4(0.f, 0.f, 0.f, 0.f);
    if (h5 == 0) {                    // self loop only on half 0
        float4 hv = *(const float4*)&h[(size_t)i * 64 + l16 * 4];
        float sl = di * di;
        acc.x = hv.x * sl; acc.y = hv.y * sl; acc.z = hv.z * sl; acc.w = hv.w * sl;
    }
    for (int e = h5; e < n; e += 2) {
        int2 sn = d_csr[base + e];
        float nrm = __int_as_float(sn.y);
        float4 hv = *(const float4*)&h[(size_t)sn.x * 64 + l16 * 4];
        acc.x = fmaf(hv.x, nrm, acc.x);
        acc.y = fmaf(hv.y, nrm, acc.y);
        acc.z = fmaf(hv.z, nrm, acc.z);
        acc.w = fmaf(hv.w, nrm, acc.w);
    }
    acc.x += __shfl_xor_sync(0xFFFFFFFFu, acc.x, 16);
    acc.y += __shfl_xor_sync(0xFFFFFFFFu, acc.y, 16);
    acc.z += __shfl_xor_sync(0xFFFFFFFFu, acc.z, 16);
    acc.w += __shfl_xor_sync(0xFFFFFFFFu, acc.w, 16);
    return acc;
}

// ---------------- fused: agg(hbuf)+b1+relu -> @W2 -> hbuf2 -------------------
// Block: 256 threads = 8 warps, 64 nodes. Phase 1: each warp aggregates 8
// nodes into smem rows. Phase 2: block does 64x64x64 GEMM from smem.
__global__ void k_agg_gemm(const float* __restrict__ hin,
                           const float* __restrict__ bias,
                           const float* __restrict__ W2,
                           float* __restrict__ hout) {
    __shared__ float as[64][65];      // 65-stride: conflict-free column reads
    __shared__ float ws[64][64];
    const int tid  = threadIdx.x;
    const int wid  = tid >> 5;
    const int lane = tid & 31;
    const int h5   = lane >> 4;
    const int l16  = lane & 15;
    const int m0   = blockIdx.x * 64;

    // stage W2 into smem
    #pragma unroll
    for (int t = tid; t < 1024; t += 256) {   // 64*64/4 float4
        int r  = t >> 4;
        int cc = (t & 15) * 4;
        *(float4*)&ws[r][cc] = *(const float4*)&W2[(size_t)r * 64 + cc];
    }

    float4 b4 = *(const float4*)&bias[l16 * 4];

    // phase 1: aggregate 8 nodes per warp
    #pragma unroll
    for (int q = 0; q < 8; q++) {
        int local = wid * 8 + q;
        int i = m0 + local;
        float4 v = make_float4(0.f, 0.f, 0.f, 0.f);
        if (i < N_NODES) {
            float4 acc = agg_node(hin, i, h5, l16);
            v.x = fmaxf(acc.x + b4.x, 0.f);
            v.y = fmaxf(acc.y + b4.y, 0.f);
            v.z = fmaxf(acc.z + b4.z, 0.f);
            v.w = fmaxf(acc.w + b4.w, 0.f);
        }
        if (h5 == 0) {
            // scalar STS: row stride 65*4B is not 16B-aligned, float4 would trap
            as[local][l16 * 4 + 0] = v.x;
            as[local][l16 * 4 + 1] = v.y;
            as[local][l16 * 4 + 2] = v.z;
            as[local][l16 * 4 + 3] = v.w;
        }
    }
    __syncthreads();

    // phase 2: [64x64] @ [64x64] register-tiled GEMM from smem
    const int tx = tid & 15;
    const int ty = tid >> 4;
    float acc[4][4] = {};
    #pragma unroll
    for (int kk = 0; kk < 64; kk++) {
        float a[4], b[4];
        #pragma unroll
        for (int i = 0; i < 4; i++) a[i] = as[ty + 16 * i][kk];
        #pragma unroll
        for (int j = 0; j < 4; j++) b[j] = ws[kk][tx + 16 * j];
        #pragma unroll
        for (int i = 0; i < 4; i++)
            #pragma unroll
            for (int j = 0; j < 4; j++)
                acc[i][j] = fmaf(a[i], b[j], acc[i][j]);
    }
    #pragma unroll
    for (int i = 0; i < 4; i++) {
        int gr = m0 + ty + 16 * i;
        if (gr < N_NODES) {
            #pragma unroll
            for (int j = 0; j < 4; j++)
                hout[(size_t)gr * 64 + tx + 16 * j] = acc[i][j];
        }
    }
}

// ---------------- fused: agg(hbuf2)+b2+relu -> @W3 -> h3 ---------------------
// Warp per node; the 64->2 GEMM is a warp dot product.
__global__ void k_agg_gemm3(const float* __restrict__ hin,
                            const float* __restrict__ bias,
                            const float* __restrict__ W3,
                            float* __restrict__ h3) {
    const int gwarp = (blockIdx.x * blockDim.x + threadIdx.x) >> 5;
    const int lane  = threadIdx.x & 31;
    if (gwarp >= N_NODES) return;
    const int i   = gwarp;
    const int h5  = lane >> 4;
    const int l16 = lane & 15;

    // per-thread W3 column slice (half h5 -> class h5)
    float w3v[4];
    #pragma unroll
    for (int j = 0; j < 4; j++)
        w3v[j] = __ldg(&W3[(l16 * 4 + j) * 2 + h5]);
    float4 b4 = *(const float4*)&bias[l16 * 4];

    float4 acc = agg_node(hin, i, h5, l16);
    float4 v;
    v.x = fmaxf(acc.x + b4.x, 0.f);
    v.y = fmaxf(acc.y + b4.y, 0.f);
    v.z = fmaxf(acc.z + b4.z, 0.f);
    v.w = fmaxf(acc.w + b4.w, 0.f);

    float p = v.x * w3v[0] + v.y * w3v[1] + v.z * w3v[2] + v.w * w3v[3];
    #pragma unroll
    for (int off = 8; off > 0; off >>= 1)
        p += __shfl_xor_sync(0xFFFFFFFFu, p, off);
    if (l16 == 0)
        h3[(size_t)i * 2 + h5] = p;
}

// ---------------- layer-3 aggregation + bias + log_softmax ------------------
__global__ void k_agg3(const float* __restrict__ h3, const float* __restrict__ b3,
                       float* __restrict__ out) {
    const int gwarp = (blockIdx.x * blockDim.x + threadIdx.x) >> 5;
    const int lane  = threadIdx.x & 31;
    if (gwarp >= N_NODES) return;
    const int i = gwarp;

    const float di = d_dinv[i];
    const int base = d_rowstart[i];
    const int n    = d_cnt[i];

    float a0 = 0.f, a1 = 0.f;
    for (int e = lane; e < n; e += 32) {
        int2 sn = d_csr[base + e];
        float nrm = __int_as_float(sn.y);
        float2 hh = *(const float2*)&h3[(size_t)sn.x * 2];
        a0 = fmaf(hh.x, nrm, a0);
        a1 = fmaf(hh.y, nrm, a1);
    }
    #pragma unroll
    for (int off = 16; off > 0; off >>= 1) {
        a0 += __shfl_down_sync(0xFFFFFFFFu, a0, off);
        a1 += __shfl_down_sync(0xFFFFFFFFu, a1, off);
    }
    if (lane == 0) {
        a0 += h3[(size_t)i * 2 + 0] * (di * di) + b3[0];
        a1 += h3[(size_t)i * 2 + 1] * (di * di) + b3[1];
        float m = fmaxf(a0, a1);
        float lse = m + logf(expf(a0 - m) + expf(a1 - m));
        out[(size_t)i * 2 + 0] = a0 - lse;
        out[(size_t)i * 2 + 1] = a1 - lse;
    }
}

// ---------------- launch -----------------------------------------------------
extern "C" void kernel_launch(void* const* d_in, const int* in_sizes, int n_in,
                              void* d_out, int out_size) {
    const float* x  = (const float*)d_in[0];
    const int*   ei = (const int*)d_in[1];
    const float* W1 = (const float*)d_in[2];
    const float* b1 = (const float*)d_in[3];
    const float* W2 = (const float*)d_in[4];
    const float* b2 = (const float*)d_in[5];
    const float* W3 = (const float*)d_in[6];
    const float* b3 = (const float*)d_in[7];
    float* out = (float*)d_out;

    const int4* src4 = (const int4*)ei;
    const int4* dst4 = (const int4*)(ei + N_EDGES);

    void *p_cnt, *p_fill, *p_cur, *p_hbuf, *p_hbuf2, *p_h3;
    cudaGetSymbolAddress(&p_cnt, d_cnt);
    cudaGetSymbolAddress(&p_fill, d_fill);
    cudaGetSymbolAddress(&p_cur, d_cursor);
    cudaGetSymbolAddress(&p_hbuf, d_hbuf);
    cudaGetSymbolAddress(&p_hbuf2, d_hbuf2);
    cudaGetSymbolAddress(&p_h3, d_h3);

    cudaMemsetAsync(p_cnt, 0, N_NODES * sizeof(int));
    cudaMemsetAsync(p_fill, 0, N_NODES * sizeof(int));
    cudaMemsetAsync(p_cur, 0, sizeof(int));

    const int NB_E4 = (N_EDGES / 4 + 255) / 256;
    const int NB_N  = (N_NODES + 255) / 256;
    const int NB_M  = (N_NODES + 63) / 64;
    const int NB_W  = (N_NODES * 32 + 255) / 256;

    // CSR build
    k_count<<<NB_E4, 256>>>(dst4);
    k_node<<<NB_N, 256>>>();
    k_fill<<<NB_E4, 256>>>(src4, dst4);

    // layer 1 GEMM
    k_gemm64<<<NB_M, 256>>>(x, W1, (float*)p_hbuf);
    // fused agg1 + b1 + relu + GEMM2
    k_agg_gemm<<<NB_M, 256>>>((const float*)p_hbuf, b1, W2, (float*)p_hbuf2);
    // fused agg2 + b2 + relu + GEMM3
    k_agg_gemm3<<<NB_W, 256>>>((const float*)p_hbuf2, b2, W3, (float*)p_h3);
    // final aggregation + log_softmax
    k_agg3<<<NB_W, 256>>>((const float*)p_h3, b3, out);
}

// round 4
// speedup vs baseline: 1.7360x; 1.1910x over previous
#include <cuda_runtime.h>
#include <math.h>
#include <stdint.h>

#define N_NODES 100000
#define N_EDGES 1600000
#define F_IN    256
#define HIDDEN  64
#define N_CLASS 2

// ---------------- scratch (static __device__; 16B-aligned for vector LDG) ---
__device__ __align__(16) float d_hbuf[N_NODES * HIDDEN];    // x@W1
__device__ __align__(16) float d_hbuf2[N_NODES * HIDDEN];   // h1@W2
__device__ __align__(16) float d_h3[N_NODES * N_CLASS];     // h2@W3
__device__ float d_dinv[N_NODES];             // deg^{-1/2}
__device__ int   d_cnt[N_NODES];              // incoming-edge count (no self loop)
__device__ int   d_fill[N_NODES];             // fill cursor
__device__ int   d_rowstart[N_NODES];         // CSR row start
__device__ __align__(16) int2 d_csr[N_EDGES]; // (src, bitcast(norm)) per incoming edge
__device__ int   d_cursor;

// ---------------- CSR build -------------------------------------------------
__global__ void k_count(const int4* __restrict__ dst4) {
    int t = blockIdx.x * blockDim.x + threadIdx.x;
    if (t < N_EDGES / 4) {
        int4 d = dst4[t];
        atomicAdd(&d_cnt[d.x], 1);
        atomicAdd(&d_cnt[d.y], 1);
        atomicAdd(&d_cnt[d.z], 1);
        atomicAdd(&d_cnt[d.w], 1);
    }
}

__global__ void k_node() {
    int i = blockIdx.x * blockDim.x + threadIdx.x;
    if (i < N_NODES) {
        int c = d_cnt[i];
        d_dinv[i] = rsqrtf((float)(c + 1));          // +1 self loop
        d_rowstart[i] = atomicAdd(&d_cursor, c);
    }
}

__global__ void k_fill(const int4* __restrict__ src4, const int4* __restrict__ dst4) {
    int t = blockIdx.x * blockDim.x + threadIdx.x;
    if (t < N_EDGES / 4) {
        int4 s = src4[t];
        int4 d = dst4[t];
        #pragma unroll
        for (int c = 0; c < 4; c++) {
            int ss = (c == 0) ? s.x : (c == 1) ? s.y : (c == 2) ? s.z : s.w;
            int dd = (c == 0) ? d.x : (c == 1) ? d.y : (c == 2) ? d.z : d.w;
            int pos = d_rowstart[dd] + atomicAdd(&d_fill[dd], 1);
            float nrm = d_dinv[ss] * d_dinv[dd];
            d_csr[pos] = make_int2(ss, __float_as_int(nrm));
        }
    }
}

// ---------------- GEMM1 (tensor core, tf32): C[M,64] = A[M,256] @ W[256,64] --
__device__ __forceinline__ uint32_t f2tf32(float x) {
    uint32_t r;
    asm("cvt.rna.tf32.f32 %0, %1;" : "=r"(r) : "f"(x));
    return r;
}

__device__ __forceinline__ void mma_tf32(float c[4], uint32_t a0, uint32_t a1,
                                         uint32_t a2, uint32_t a3,
                                         uint32_t b0, uint32_t b1) {
    asm volatile(
        "mma.sync.aligned.m16n8k8.row.col.f32.tf32.tf32.f32 "
        "{%0,%1,%2,%3}, {%4,%5,%6,%7}, {%8,%9}, {%0,%1,%2,%3};"
        : "+f"(c[0]), "+f"(c[1]), "+f"(c[2]), "+f"(c[3])
        : "r"(a0), "r"(a1), "r"(a2), "r"(a3), "r"(b0), "r"(b1));
}

// block: 256 threads = 8 warps; tile M=128, N=64; K staged in chunks of 32.
__global__ void k_gemm_tc(const float* __restrict__ A, const float* __restrict__ W,
                          float* __restrict__ C) {
    __shared__ uint32_t as[128][36];   // stride 36: a-frag banks 4g+tg distinct
    __shared__ uint32_t ws[32][72];    // stride 72: b-frag banks 8tg+g distinct
    const int tid  = threadIdx.x;
    const int wrp  = tid >> 5;
    const int lane = tid & 31;
    const int g    = lane >> 2;        // groupID
    const int tg   = lane & 3;         // threadID in group
    const int m0   = blockIdx.x * 128;

    float acc[8][4];
    #pragma unroll
    for (int j = 0; j < 8; j++)
        #pragma unroll
        for (int q = 0; q < 4; q++) acc[j][q] = 0.f;

    for (int k0 = 0; k0 < F_IN; k0 += 32) {
        // stage A chunk 128x32 (tf32 bits)
        #pragma unroll
        for (int t = tid; t < 1024; t += 256) {
            int r  = t >> 3;
            int c4 = (t & 7) * 4;
            int gr = m0 + r;
            float4 v = make_float4(0.f, 0.f, 0.f, 0.f);
            if (gr < N_NODES)
                v = *(const float4*)&A[(size_t)gr * F_IN + k0 + c4];
            uint4 u = make_uint4(f2tf32(v.x), f2tf32(v.y), f2tf32(v.z), f2tf32(v.w));
            *(uint4*)&as[r][c4] = u;
        }
        // stage W chunk 32x64 (tf32 bits)
        #pragma unroll
        for (int t = tid; t < 512; t += 256) {
            int r  = t >> 4;
            int c4 = (t & 15) * 4;
            float4 v = *(const float4*)&W[(size_t)(k0 + r) * 64 + c4];
            uint4 u = make_uint4(f2tf32(v.x), f2tf32(v.y), f2tf32(v.z), f2tf32(v.w));
            *(uint4*)&ws[r][c4] = u;
        }
        __syncthreads();

        #pragma unroll
        for (int kk = 0; kk < 32; kk += 8) {
            uint32_t a0 = as[wrp * 16 + g][kk + tg];
            uint32_t a1 = as[wrp * 16 + g + 8][kk + tg];
            uint32_t a2 = as[wrp * 16 + g][kk + tg + 4];
            uint32_t a3 = as[wrp * 16 + g + 8][kk + tg + 4];
            #pragma unroll
            for (int j = 0; j < 8; j++) {
                uint32_t b0 = ws[kk + tg][8 * j + g];
                uint32_t b1 = ws[kk + tg + 4][8 * j + g];
                mma_tf32(acc[j], a0, a1, a2, a3, b0, b1);
            }
        }
        __syncthreads();
    }

    // store: c0/c1 at [g][2tg,2tg+1], c2/c3 at [g+8][...]
    const int row0 = m0 + wrp * 16 + g;
    #pragma unroll
    for (int j = 0; j < 8; j++) {
        int col = 8 * j + 2 * tg;
        if (row0 < N_NODES)
            *(float2*)&C[(size_t)row0 * 64 + col] = make_float2(acc[j][0], acc[j][1]);
        if (row0 + 8 < N_NODES)
            *(float2*)&C[(size_t)(row0 + 8) * 64 + col] = make_float2(acc[j][2], acc[j][3]);
    }
}

// ---------------- warp-level 64-wide aggregation core -----------------------
// Warp: two 16-lane halves, each half processes a different edge per step.
// Lane l16 of each half holds feats [l16*4 .. l16*4+3] as float4.
// After the loop, shfl_xor(16) leaves the full sum in ALL 32 lanes.
__device__ __forceinline__ float4 agg_node(const float* __restrict__ h, int i,
                                           int h5 /*0 or 1*/, int l16) {
    const float di = d_dinv[i];
    const int base = d_rowstart[i];
    const int n    = d_cnt[i];

    float4 acc = make_float4(0.f, 0.f, 0.f, 0.f);
    if (h5 == 0) {                    // self loop only on half 0
        float4 hv = *(const float4*)&h[(size_t)i * 64 + l16 * 4];
        float sl = di * di;
        acc.x = hv.x * sl; acc.y = hv.y * sl; acc.z = hv.z * sl; acc.w = hv.w * sl;
    }
    #pragma unroll 2
    for (int e = h5; e < n; e += 2) {
        int2 sn = d_csr[base + e];
        float nrm = __int_as_float(sn.y);
        float4 hv = *(const float4*)&h[(size_t)sn.x * 64 + l16 * 4];
        acc.x = fmaf(hv.x, nrm, acc.x);
        acc.y = fmaf(hv.y, nrm, acc.y);
        acc.z = fmaf(hv.z, nrm, acc.z);
        acc.w = fmaf(hv.w, nrm, acc.w);
    }
    acc.x += __shfl_xor_sync(0xFFFFFFFFu, acc.x, 16);
    acc.y += __shfl_xor_sync(0xFFFFFFFFu, acc.y, 16);
    acc.z += __shfl_xor_sync(0xFFFFFFFFu, acc.z, 16);
    acc.w += __shfl_xor_sync(0xFFFFFFFFu, acc.w, 16);
    return acc;
}

// ---------------- fused: agg(hbuf)+b1+relu -> @W2 -> hbuf2 -------------------
__global__ void k_agg_gemm(const float* __restrict__ hin,
                           const float* __restrict__ bias,
                           const float* __restrict__ W2,
                           float* __restrict__ hout) {
    __shared__ float as[64][65];      // 65-stride: conflict-free column reads
    __shared__ float ws[64][64];
    const int tid  = threadIdx.x;
    const int wid  = tid >> 5;
    const int lane = tid & 31;
    const int h5   = lane >> 4;
    const int l16  = lane & 15;
    const int m0   = blockIdx.x * 64;

    // stage W2 into smem
    #pragma unroll
    for (int t = tid; t < 1024; t += 256) {   // 64*64/4 float4
        int r  = t >> 4;
        int cc = (t & 15) * 4;
        *(float4*)&ws[r][cc] = *(const float4*)&W2[(size_t)r * 64 + cc];
    }

    float4 b4 = *(const float4*)&bias[l16 * 4];

    // phase 1: aggregate 8 nodes per warp
    #pragma unroll
    for (int q = 0; q < 8; q++) {
        int local = wid * 8 + q;
        int i = m0 + local;
        float4 v = make_float4(0.f, 0.f, 0.f, 0.f);
        if (i < N_NODES) {
            float4 acc = agg_node(hin, i, h5, l16);
            v.x = fmaxf(acc.x + b4.x, 0.f);
            v.y = fmaxf(acc.y + b4.y, 0.f);
            v.z = fmaxf(acc.z + b4.z, 0.f);
            v.w = fmaxf(acc.w + b4.w, 0.f);
        }
        if (h5 == 0) {
            // scalar STS: row stride 65*4B is not 16B-aligned, float4 would trap
            as[local][l16 * 4 + 0] = v.x;
            as[local][l16 * 4 + 1] = v.y;
            as[local][l16 * 4 + 2] = v.z;
            as[local][l16 * 4 + 3] = v.w;
        }
    }
    __syncthreads();

    // phase 2: [64x64] @ [64x64] register-tiled GEMM from smem
    const int tx = tid & 15;
    const int ty = tid >> 4;
    float acc[4][4] = {};
    #pragma unroll
    for (int kk = 0; kk < 64; kk++) {
        float a[4], b[4];
        #pragma unroll
        for (int i = 0; i < 4; i++) a[i] = as[ty + 16 * i][kk];
        #pragma unroll
        for (int j = 0; j < 4; j++) b[j] = ws[kk][tx + 16 * j];
        #pragma unroll
        for (int i = 0; i < 4; i++)
            #pragma unroll
            for (int j = 0; j < 4; j++)
                acc[i][j] = fmaf(a[i], b[j], acc[i][j]);
    }
    #pragma unroll
    for (int i = 0; i < 4; i++) {
        int gr = m0 + ty + 16 * i;
        if (gr < N_NODES) {
            #pragma unroll
            for (int j = 0; j < 4; j++)
                hout[(size_t)gr * 64 + tx + 16 * j] = acc[i][j];
        }
    }
}

// ---------------- fused: agg(hbuf2)+b2+relu -> @W3 -> h3 ---------------------
__global__ void k_agg_gemm3(const float* __restrict__ hin,
                            const float* __restrict__ bias,
                            const float* __restrict__ W3,
                            float* __restrict__ h3) {
    const int gwarp = (blockIdx.x * blockDim.x + threadIdx.x) >> 5;
    const int lane  = threadIdx.x & 31;
    if (gwarp >= N_NODES) return;
    const int i   = gwarp;
    const int h5  = lane >> 4;
    const int l16 = lane & 15;

    // per-thread W3 column slice (half h5 -> class h5)
    float w3v[4];
    #pragma unroll
    for (int j = 0; j < 4; j++)
        w3v[j] = __ldg(&W3[(l16 * 4 + j) * 2 + h5]);
    float4 b4 = *(const float4*)&bias[l16 * 4];

    float4 acc = agg_node(hin, i, h5, l16);
    float4 v;
    v.x = fmaxf(acc.x + b4.x, 0.f);
    v.y = fmaxf(acc.y + b4.y, 0.f);
    v.z = fmaxf(acc.z + b4.z, 0.f);
    v.w = fmaxf(acc.w + b4.w, 0.f);

    float p = v.x * w3v[0] + v.y * w3v[1] + v.z * w3v[2] + v.w * w3v[3];
    #pragma unroll
    for (int off = 8; off > 0; off >>= 1)
        p += __shfl_xor_sync(0xFFFFFFFFu, p, off);
    if (l16 == 0)
        h3[(size_t)i * 2 + h5] = p;
}

// ---------------- layer-3 aggregation + bias + log_softmax ------------------
__global__ void k_agg3(const float* __restrict__ h3, const float* __restrict__ b3,
                       float* __restrict__ out) {
    const int gwarp = (blockIdx.x * blockDim.x + threadIdx.x) >> 5;
    const int lane  = threadIdx.x & 31;
    if (gwarp >= N_NODES) return;
    const int i = gwarp;

    const float di = d_dinv[i];
    const int base = d_rowstart[i];
    const int n    = d_cnt[i];

    float a0 = 0.f, a1 = 0.f;
    for (int e = lane; e < n; e += 32) {
        int2 sn = d_csr[base + e];
        float nrm = __int_as_float(sn.y);
        float2 hh = *(const float2*)&h3[(size_t)sn.x * 2];
        a0 = fmaf(hh.x, nrm, a0);
        a1 = fmaf(hh.y, nrm, a1);
    }
    #pragma unroll
    for (int off = 16; off > 0; off >>= 1) {
        a0 += __shfl_down_sync(0xFFFFFFFFu, a0, off);
        a1 += __shfl_down_sync(0xFFFFFFFFu, a1, off);
    }
    if (lane == 0) {
        a0 += h3[(size_t)i * 2 + 0] * (di * di) + b3[0];
        a1 += h3[(size_t)i * 2 + 1] * (di * di) + b3[1];
        float m = fmaxf(a0, a1);
        float lse = m + logf(expf(a0 - m) + expf(a1 - m));
        out[(size_t)i * 2 + 0] = a0 - lse;
        out[(size_t)i * 2 + 1] = a1 - lse;
    }
}

// ---------------- launch -----------------------------------------------------
extern "C" void kernel_launch(void* const* d_in, const int* in_sizes, int n_in,
                              void* d_out, int out_size) {
    const float* x  = (const float*)d_in[0];
    const int*   ei = (const int*)d_in[1];
    const float* W1 = (const float*)d_in[2];
    const float* b1 = (const float*)d_in[3];
    const float* W2 = (const float*)d_in[4];
    const float* b2 = (const float*)d_in[5];
    const float* W3 = (const float*)d_in[6];
    const float* b3 = (const float*)d_in[7];
    float* out = (float*)d_out;

    const int4* src4 = (const int4*)ei;
    const int4* dst4 = (const int4*)(ei + N_EDGES);

    void *p_cnt, *p_fill, *p_cur, *p_hbuf, *p_hbuf2, *p_h3;
    cudaGetSymbolAddress(&p_cnt, d_cnt);
    cudaGetSymbolAddress(&p_fill, d_fill);
    cudaGetSymbolAddress(&p_cur, d_cursor);
    cudaGetSymbolAddress(&p_hbuf, d_hbuf);
    cudaGetSymbolAddress(&p_hbuf2, d_hbuf2);
    cudaGetSymbolAddress(&p_h3, d_h3);

    cudaMemsetAsync(p_cnt, 0, N_NODES * sizeof(int));
    cudaMemsetAsync(p_fill, 0, N_NODES * sizeof(int));
    cudaMemsetAsync(p_cur, 0, sizeof(int));

    const int NB_E4 = (N_EDGES / 4 + 255) / 256;
    const int NB_N  = (N_NODES + 255) / 256;
    const int NB_T  = (N_NODES + 127) / 128;       // tensor-core GEMM tiles
    const int NB_M  = (N_NODES + 63) / 64;
    const int NB_W  = (N_NODES * 32 + 255) / 256;

    // CSR build
    k_count<<<NB_E4, 256>>>(dst4);
    k_node<<<NB_N, 256>>>();
    k_fill<<<NB_E4, 256>>>(src4, dst4);

    // layer 1 GEMM (tf32 tensor cores)
    k_gemm_tc<<<NB_T, 256>>>(x, W1, (float*)p_hbuf);
    // fused agg1 + b1 + relu + GEMM2
    k_agg_gemm<<<NB_M, 256>>>((const float*)p_hbuf, b1, W2, (float*)p_hbuf2);
    // fused agg2 + b2 + relu + GEMM3
    k_agg_gemm3<<<NB_W, 256>>>((const float*)p_hbuf2, b2, W3, (float*)p_h3);
    // final aggregation + log_softmax
    k_agg3<<<NB_W, 256>>>((const float*)p_h3, b3, out);
}

// round 6
// speedup vs baseline: 1.9587x; 1.1282x over previous
#include <cuda_runtime.h>
#include <math.h>
#include <stdint.h>

#define N_NODES 100000
#define N_EDGES 1600000
#define F_IN    256
#define HIDDEN  64
#define N_CLASS 2

// ---------------- scratch (static __device__; 16B-aligned for vector LDG) ---
__device__ __align__(16) float d_hbuf[N_NODES * HIDDEN];    // x@W1
__device__ __align__(16) float d_hbuf2[N_NODES * HIDDEN];   // h1@W2
__device__ __align__(16) float d_h3[N_NODES * N_CLASS];     // h2@W3
__device__ float d_dinv[N_NODES];             // deg^{-1/2}
__device__ int   d_cnt[N_NODES];              // incoming-edge count (no self loop)
__device__ int   d_fill[N_NODES];             // fill cursor
__device__ int   d_rowstart[N_NODES];         // CSR row start
__device__ __align__(16) int2 d_csr[N_EDGES]; // (src, bitcast(norm)) per incoming edge
__device__ int   d_cursor;

// ---------------- CSR build -------------------------------------------------
__global__ void k_count(const int4* __restrict__ dst4) {
    int t = blockIdx.x * blockDim.x + threadIdx.x;
    if (t < N_EDGES / 4) {
        int4 d = dst4[t];
        atomicAdd(&d_cnt[d.x], 1);
        atomicAdd(&d_cnt[d.y], 1);
        atomicAdd(&d_cnt[d.z], 1);
        atomicAdd(&d_cnt[d.w], 1);
    }
}

__global__ void k_node() {
    int i = blockIdx.x * blockDim.x + threadIdx.x;
    if (i < N_NODES) {
        int c = d_cnt[i];
        d_dinv[i] = rsqrtf((float)(c + 1));          // +1 self loop
        d_rowstart[i] = atomicAdd(&d_cursor, c);
    }
}

__global__ void k_fill(const int4* __restrict__ src4, const int4* __restrict__ dst4) {
    int t = blockIdx.x * blockDim.x + threadIdx.x;
    if (t < N_EDGES / 4) {
        int4 s = src4[t];
        int4 d = dst4[t];
        #pragma unroll
        for (int c = 0; c < 4; c++) {
            int ss = (c == 0) ? s.x : (c == 1) ? s.y : (c == 2) ? s.z : s.w;
            int dd = (c == 0) ? d.x : (c == 1) ? d.y : (c == 2) ? d.z : d.w;
            int pos = d_rowstart[dd] + atomicAdd(&d_fill[dd], 1);
            float nrm = d_dinv[ss] * d_dinv[dd];
            d_csr[pos] = make_int2(ss, __float_as_int(nrm));
        }
    }
}

// ---------------- GEMM1 (tensor core, tf32): C[M,64] = A[M,256] @ W[256,64] --
__device__ __forceinline__ uint32_t f2tf32(float x) {
    uint32_t r;
    asm("cvt.rna.tf32.f32 %0, %1;" : "=r"(r) : "f"(x));
    return r;
}

__device__ __forceinline__ void mma_tf32(float c[4], uint32_t a0, uint32_t a1,
                                         uint32_t a2, uint32_t a3,
                                         uint32_t b0, uint32_t b1) {
    asm volatile(
        "mma.sync.aligned.m16n8k8.row.col.f32.tf32.tf32.f32 "
        "{%0,%1,%2,%3}, {%4,%5,%6,%7}, {%8,%9}, {%0,%1,%2,%3};"
        : "+f"(c[0]), "+f"(c[1]), "+f"(c[2]), "+f"(c[3])
        : "r"(a0), "r"(a1), "r"(a2), "r"(a3), "r"(b0), "r"(b1));
}

// block: 256 threads = 8 warps; tile M=128, N=64; K in chunks of 32,
// double-buffered smem + register prefetch: LDG(c+1) overlaps MMA(c).
#define N_CHUNKS (F_IN / 32)
__global__ void k_gemm_tc(const float* __restrict__ A, const float* __restrict__ W,
                          float* __restrict__ C) {
    __shared__ uint32_t as[2][128][36];   // stride 36: a-frag banks conflict-free
    __shared__ uint32_t ws[2][32][72];    // stride 72: b-frag banks conflict-free
    const int tid  = threadIdx.x;
    const int wrp  = tid >> 5;
    const int lane = tid & 31;
    const int g    = lane >> 2;
    const int tg   = lane & 3;
    const int m0   = blockIdx.x * 128;

    // per-thread staging coords (fixed across chunks)
    const int ar[4] = { tid >> 3, (tid + 256) >> 3, (tid + 512) >> 3, (tid + 768) >> 3 };
    const int ac    = (tid & 7) * 4;
    const int wr0   = tid >> 4;            // rows 0..15
    const int wr1   = (tid + 256) >> 4;    // rows 16..31
    const int wc    = (tid & 15) * 4;

    float4 aR[4];
    float4 wR[2];

    // LDG chunk k0 into registers
    auto ldg_chunk = [&](int c) {
        const int k0 = c * 32;
        #pragma unroll
        for (int i = 0; i < 4; i++) {
            int gr = m0 + ar[i];
            aR[i] = make_float4(0.f, 0.f, 0.f, 0.f);
            if (gr < N_NODES)
                aR[i] = *(const float4*)&A[(size_t)gr * F_IN + k0 + ac];
        }
        wR[0] = *(const float4*)&W[(size_t)(k0 + wr0) * 64 + wc];
        wR[1] = *(const float4*)&W[(size_t)(k0 + wr1) * 64 + wc];
    };
    auto sts_chunk = [&](int buf) {
        #pragma unroll
        for (int i = 0; i < 4; i++)
            *(uint4*)&as[buf][ar[i]][ac] = make_uint4(
                f2tf32(aR[i].x), f2tf32(aR[i].y), f2tf32(aR[i].z), f2tf32(aR[i].w));
        *(uint4*)&ws[buf][wr0][wc] = make_uint4(
            f2tf32(wR[0].x), f2tf32(wR[0].y), f2tf32(wR[0].z), f2tf32(wR[0].w));
        *(uint4*)&ws[buf][wr1][wc] = make_uint4(
            f2tf32(wR[1].x), f2tf32(wR[1].y), f2tf32(wR[1].z), f2tf32(wR[1].w));
    };

    float acc[8][4];
    #pragma unroll
    for (int j = 0; j < 8; j++)
        #pragma unroll
        for (int q = 0; q < 4; q++) acc[j][q] = 0.f;

    ldg_chunk(0);
    sts_chunk(0);
    __syncthreads();

    #pragma unroll
    for (int c = 0; c < N_CHUNKS; c++) {
        const int buf = c & 1;
        if (c < N_CHUNKS - 1)
            ldg_chunk(c + 1);                 // in flight under the MMAs below

        #pragma unroll
        for (int kk = 0; kk < 32; kk += 8) {
            uint32_t a0 = as[buf][wrp * 16 + g][kk + tg];
            uint32_t a1 = as[buf][wrp * 16 + g + 8][kk + tg];
            uint32_t a2 = as[buf][wrp * 16 + g][kk + tg + 4];
            uint32_t a3 = as[buf][wrp * 16 + g + 8][kk + tg + 4];
            #pragma unroll
            for (int j = 0; j < 8; j++) {
                uint32_t b0 = ws[buf][kk + tg][8 * j + g];
                uint32_t b1 = ws[buf][kk + tg + 4][8 * j + g];
                mma_tf32(acc[j], a0, a1, a2, a3, b0, b1);
            }
        }

        if (c < N_CHUNKS - 1) {
            sts_chunk(buf ^ 1);               // waits on LDG data only
            __syncthreads();                  // one barrier per chunk
        }
    }

    const int row0 = m0 + wrp * 16 + g;
    #pragma unroll
    for (int j = 0; j < 8; j++) {
        int col = 8 * j + 2 * tg;
        if (row0 < N_NODES)
            *(float2*)&C[(size_t)row0 * 64 + col] = make_float2(acc[j][0], acc[j][1]);
        if (row0 + 8 < N_NODES)
            *(float2*)&C[(size_t)(row0 + 8) * 64 + col] = make_float2(acc[j][2], acc[j][3]);
    }
}

// ---------------- warp-level 64-wide aggregation core -----------------------
// Warp: two 16-lane halves, each half processes a different edge per step.
// Lane l16 of each half holds feats [l16*4 .. l16*4+3] as float4.
// After the loop, shfl_xor(16) leaves the full sum in ALL 32 lanes.
__device__ __forceinline__ float4 agg_node(const float* __restrict__ h, int i,
                                           int h5 /*0 or 1*/, int l16) {
    const float di = d_dinv[i];
    const int base = d_rowstart[i];
    const int n    = d_cnt[i];

    float4 acc = make_float4(0.f, 0.f, 0.f, 0.f);
    if (h5 == 0) {                    // self loop only on half 0
        float4 hv = *(const float4*)&h[(size_t)i * 64 + l16 * 4];
        float sl = di * di;
        acc.x = hv.x * sl; acc.y = hv.y * sl; acc.z = hv.z * sl; acc.w = hv.w * sl;
    }
    #pragma unroll 4
    for (int e = h5; e < n; e += 2) {
        int2 sn = d_csr[base + e];
        float nrm = __int_as_float(sn.y);
        float4 hv = *(const float4*)&h[(size_t)sn.x * 64 + l16 * 4];
        acc.x = fmaf(hv.x, nrm, acc.x);
        acc.y = fmaf(hv.y, nrm, acc.y);
        acc.z = fmaf(hv.z, nrm, acc.z);
        acc.w = fmaf(hv.w, nrm, acc.w);
    }
    acc.x += __shfl_xor_sync(0xFFFFFFFFu, acc.x, 16);
    acc.y += __shfl_xor_sync(0xFFFFFFFFu, acc.y, 16);
    acc.z += __shfl_xor_sync(0xFFFFFFFFu, acc.z, 16);
    acc.w += __shfl_xor_sync(0xFFFFFFFFu, acc.w, 16);
    return acc;
}

// ---------------- fused: agg(hbuf)+b1+relu -> @W2 -> hbuf2 -------------------
__global__ void k_agg_gemm(const float* __restrict__ hin,
                           const float* __restrict__ bias,
                           const float* __restrict__ W2,
                           float* __restrict__ hout) {
    __shared__ float as[64][65];      // 65-stride: conflict-free column reads
    __shared__ float ws[64][64];
    const int tid  = threadIdx.x;
    const int wid  = tid >> 5;
    const int lane = tid & 31;
    const int h5   = lane >> 4;
    const int l16  = lane & 15;
    const int m0   = blockIdx.x * 64;

    // stage W2 into smem
    #pragma unroll
    for (int t = tid; t < 1024; t += 256) {   // 64*64/4 float4
        int r  = t >> 4;
        int cc = (t & 15) * 4;
        *(float4*)&ws[r][cc] = *(const float4*)&W2[(size_t)r * 64 + cc];
    }

    float4 b4 = *(const float4*)&bias[l16 * 4];

    // phase 1: aggregate 8 nodes per warp
    #pragma unroll
    for (int q = 0; q < 8; q++) {
        int local = wid * 8 + q;
        int i = m0 + local;
        float4 v = make_float4(0.f, 0.f, 0.f, 0.f);
        if (i < N_NODES) {
            float4 acc = agg_node(hin, i, h5, l16);
            v.x = fmaxf(acc.x + b4.x, 0.f);
            v.y = fmaxf(acc.y + b4.y, 0.f);
            v.z = fmaxf(acc.z + b4.z, 0.f);
            v.w = fmaxf(acc.w + b4.w, 0.f);
        }
        if (h5 == 0) {
            // scalar STS: row stride 65*4B is not 16B-aligned, float4 would trap
            as[local][l16 * 4 + 0] = v.x;
            as[local][l16 * 4 + 1] = v.y;
            as[local][l16 * 4 + 2] = v.z;
            as[local][l16 * 4 + 3] = v.w;
        }
    }
    __syncthreads();

    // phase 2: [64x64] @ [64x64] register-tiled GEMM from smem
    const int tx = tid & 15;
    const int ty = tid >> 4;
    float acc[4][4] = {};
    #pragma unroll
    for (int kk = 0; kk < 64; kk++) {
        float a[4], b[4];
        #pragma unroll
        for (int i = 0; i < 4; i++) a[i] = as[ty + 16 * i][kk];
        #pragma unroll
        for (int j = 0; j < 4; j++) b[j] = ws[kk][tx + 16 * j];
        #pragma unroll
        for (int i = 0; i < 4; i++)
            #pragma unroll
            for (int j = 0; j < 4; j++)
                acc[i][j] = fmaf(a[i], b[j], acc[i][j]);
    }
    #pragma unroll
    for (int i = 0; i < 4; i++) {
        int gr = m0 + ty + 16 * i;
        if (gr < N_NODES) {
            #pragma unroll
            for (int j = 0; j < 4; j++)
                hout[(size_t)gr * 64 + tx + 16 * j] = acc[i][j];
        }
    }
}

// ---------------- fused: agg(hbuf2)+b2+relu -> @W3 -> h3 ---------------------
__global__ void k_agg_gemm3(const float* __restrict__ hin,
                            const float* __restrict__ bias,
                            const float* __restrict__ W3,
                            float* __restrict__ h3) {
    const int gwarp = (blockIdx.x * blockDim.x + threadIdx.x) >> 5;
    const int lane  = threadIdx.x & 31;
    if (gwarp >= N_NODES) return;
    const int i   = gwarp;
    const int h5  = lane >> 4;
    const int l16 = lane & 15;

    // per-thread W3 column slice (half h5 -> class h5)
    float w3v[4];
    #pragma unroll
    for (int j = 0; j < 4; j++)
        w3v[j] = __ldg(&W3[(l16 * 4 + j) * 2 + h5]);
    float4 b4 = *(const float4*)&bias[l16 * 4];

    float4 acc = agg_node(hin, i, h5, l16);
    float4 v;
    v.x = fmaxf(acc.x + b4.x, 0.f);
    v.y = fmaxf(acc.y + b4.y, 0.f);
    v.z = fmaxf(acc.z + b4.z, 0.f);
    v.w = fmaxf(acc.w + b4.w, 0.f);

    float p = v.x * w3v[0] + v.y * w3v[1] + v.z * w3v[2] + v.w * w3v[3];
    #pragma unroll
    for (int off = 8; off > 0; off >>= 1)
        p += __shfl_xor_sync(0xFFFFFFFFu, p, off);
    if (l16 == 0)
        h3[(size_t)i * 2 + h5] = p;
}

// ---------------- layer-3 aggregation + bias + log_softmax ------------------
__global__ void k_agg3(const float* __restrict__ h3, const float* __restrict__ b3,
                       float* __restrict__ out) {
    const int gwarp = (blockIdx.x * blockDim.x + threadIdx.x) >> 5;
    const int lane  = threadIdx.x & 31;
    if (gwarp >= N_NODES) return;
    const int i = gwarp;

    const float di = d_dinv[i];
    const int base = d_rowstart[i];
    const int n    = d_cnt[i];

    float a0 = 0.f, a1 = 0.f;
    for (int e = lane; e < n; e += 32) {
        int2 sn = d_csr[base + e];
        float nrm = __int_as_float(sn.y);
        float2 hh = *(const float2*)&h3[(size_t)sn.x * 2];
        a0 = fmaf(hh.x, nrm, a0);
        a1 = fmaf(hh.y, nrm, a1);
    }
    #pragma unroll
    for (int off = 16; off > 0; off >>= 1) {
        a0 += __shfl_down_sync(0xFFFFFFFFu, a0, off);
        a1 += __shfl_down_sync(0xFFFFFFFFu, a1, off);
    }
    if (lane == 0) {
        a0 += h3[(size_t)i * 2 + 0] * (di * di) + b3[0];
        a1 += h3[(size_t)i * 2 + 1] * (di * di) + b3[1];
        float m = fmaxf(a0, a1);
        float lse = m + logf(expf(a0 - m) + expf(a1 - m));
        out[(size_t)i * 2 + 0] = a0 - lse;
        out[(size_t)i * 2 + 1] = a1 - lse;
    }
}

// ---------------- launch -----------------------------------------------------
extern "C" void kernel_launch(void* const* d_in, const int* in_sizes, int n_in,
                              void* d_out, int out_size) {
    const float* x  = (const float*)d_in[0];
    const int*   ei = (const int*)d_in[1];
    const float* W1 = (const float*)d_in[2];
    const float* b1 = (const float*)d_in[3];
    const float* W2 = (const float*)d_in[4];
    const float* b2 = (const float*)d_in[5];
    const float* W3 = (const float*)d_in[6];
    const float* b3 = (const float*)d_in[7];
    float* out = (float*)d_out;

    const int4* src4 = (const int4*)ei;
    const int4* dst4 = (const int4*)(ei + N_EDGES);

    void *p_cnt, *p_fill, *p_cur, *p_hbuf, *p_hbuf2, *p_h3;
    cudaGetSymbolAddress(&p_cnt, d_cnt);
    cudaGetSymbolAddress(&p_fill, d_fill);
    cudaGetSymbolAddress(&p_cur, d_cursor);
    cudaGetSymbolAddress(&p_hbuf, d_hbuf);
    cudaGetSymbolAddress(&p_hbuf2, d_hbuf2);
    cudaGetSymbolAddress(&p_h3, d_h3);

    cudaMemsetAsync(p_cnt, 0, N_NODES * sizeof(int));
    cudaMemsetAsync(p_fill, 0, N_NODES * sizeof(int));
    cudaMemsetAsync(p_cur, 0, sizeof(int));

    const int NB_E4 = (N_EDGES / 4 + 255) / 256;
    const int NB_N  = (N_NODES + 255) / 256;
    const int NB_T  = (N_NODES + 127) / 128;       // tensor-core GEMM tiles
    const int NB_M  = (N_NODES + 63) / 64;
    const int NB_W  = (N_NODES * 32 + 255) / 256;

    // CSR build
    k_count<<<NB_E4, 256>>>(dst4);
    k_node<<<NB_N, 256>>>();
    k_fill<<<NB_E4, 256>>>(src4, dst4);

    // layer 1 GEMM (tf32 tensor cores, double-buffered pipeline)
    k_gemm_tc<<<NB_T, 256>>>(x, W1, (float*)p_hbuf);
    // fused agg1 + b1 + relu + GEMM2
    k_agg_gemm<<<NB_M, 256>>>((const float*)p_hbuf, b1, W2, (float*)p_hbuf2);
    // fused agg2 + b2 + relu + GEMM3
    k_agg_gemm3<<<NB_W, 256>>>((const float*)p_hbuf2, b2, W3, (float*)p_h3);
    // final aggregation + log_softmax
    k_agg3<<<NB_W, 256>>>((const float*)p_h3, b3, out);
}

// round 7
// speedup vs baseline: 2.0654x; 1.0545x over previous
#include <cuda_runtime.h>
#include <math.h>
#include <stdint.h>

#define N_NODES 100000
#define N_EDGES 1600000
#define F_IN    256
#define HIDDEN  64
#define N_CLASS 2

// ---------------- scratch (static __device__; 16B-aligned for vector LDG) ---
__device__ __align__(16) float d_hbuf[N_NODES * HIDDEN];    // x@W1
__device__ __align__(16) float d_hbuf2[N_NODES * HIDDEN];   // h1@W2
__device__ __align__(16) float d_h3[N_NODES * N_CLASS];     // h2@W3
__device__ float d_dinv[N_NODES];             // deg^{-1/2}
__device__ int   d_cnt[N_NODES];              // incoming-edge count (no self loop)
__device__ int   d_rowstart[N_NODES];         // CSR cursor: start, then end after fill
__device__ __align__(16) int2 d_csr[N_EDGES]; // (src, bitcast(norm)) per incoming edge
__device__ int   d_cursor;

// ---------------- CSR build -------------------------------------------------
__global__ void k_count(const int4* __restrict__ dst4) {
    int t = blockIdx.x * blockDim.x + threadIdx.x;
    if (t < N_EDGES / 4) {
        int4 d = dst4[t];
        atomicAdd(&d_cnt[d.x], 1);
        atomicAdd(&d_cnt[d.y], 1);
        atomicAdd(&d_cnt[d.z], 1);
        atomicAdd(&d_cnt[d.w], 1);
    }
}

__global__ void k_node() {
    int i = blockIdx.x * blockDim.x + threadIdx.x;
    if (i < N_NODES) {
        int c = d_cnt[i];
        d_dinv[i] = rsqrtf((float)(c + 1));          // +1 self loop
        d_rowstart[i] = atomicAdd(&d_cursor, c);
    }
}

// fill bumps d_rowstart in place; afterwards rowstart[i] = row END,
// aggregation recomputes base = rowstart[i] - cnt[i].
__global__ void k_fill(const int4* __restrict__ src4, const int4* __restrict__ dst4) {
    int t = blockIdx.x * blockDim.x + threadIdx.x;
    if (t < N_EDGES / 4) {
        int4 s = src4[t];
        int4 d = dst4[t];
        #pragma unroll
        for (int c = 0; c < 4; c++) {
            int ss = (c == 0) ? s.x : (c == 1) ? s.y : (c == 2) ? s.z : s.w;
            int dd = (c == 0) ? d.x : (c == 1) ? d.y : (c == 2) ? d.z : d.w;
            int pos = atomicAdd(&d_rowstart[dd], 1);
            float nrm = d_dinv[ss] * d_dinv[dd];
            d_csr[pos] = make_int2(ss, __float_as_int(nrm));
        }
    }
}

// ---------------- GEMM1 (tensor core, tf32): C[M,64] = A[M,256] @ W[256,64] --
// fp32 bit patterns are fed to the tf32 MMA directly (HW uses the 19 tf32
// bits; RZ truncation) — no cvt, no register staging.
__device__ __forceinline__ uint32_t smem_u32(const void* p) {
    return (uint32_t)__cvta_generic_to_shared(p);
}
__device__ __forceinline__ void cp_async16(uint32_t dst, const void* src) {
    asm volatile("cp.async.ca.shared.global [%0], [%1], 16;" :: "r"(dst), "l"(src));
}

__device__ __forceinline__ void mma_tf32(float c[4], uint32_t a0, uint32_t a1,
                                         uint32_t a2, uint32_t a3,
                                         uint32_t b0, uint32_t b1) {
    asm volatile(
        "mma.sync.aligned.m16n8k8.row.col.f32.tf32.tf32.f32 "
        "{%0,%1,%2,%3}, {%4,%5,%6,%7}, {%8,%9}, {%0,%1,%2,%3};"
        : "+f"(c[0]), "+f"(c[1]), "+f"(c[2]), "+f"(c[3])
        : "r"(a0), "r"(a1), "r"(a2), "r"(a3), "r"(b0), "r"(b1));
}

// block: 256 threads = 8 warps; tile M=128, N=64; K in chunks of 32,
// double-buffered cp.async pipeline.
#define N_CHUNKS (F_IN / 32)
__global__ void k_gemm_tc(const float* __restrict__ A, const float* __restrict__ W,
                          float* __restrict__ C) {
    __shared__ uint32_t as[2][128][36];   // stride 36: a-frag conflict-free
    __shared__ uint32_t ws[2][32][72];    // stride 72: b-frag conflict-free
    const int tid  = threadIdx.x;
    const int wrp  = tid >> 5;
    const int lane = tid & 31;
    const int g    = lane >> 2;
    const int tg   = lane & 3;
    const int m0   = blockIdx.x * 128;

    // staging coords
    const int ar = tid >> 3;          // A rows ar, ar+32, ar+64, ar+96
    const int ac = (tid & 7) * 4;     // float col within 32-wide chunk
    const int wr = tid >> 4;          // W rows wr, wr+16
    const int wc = (tid & 15) * 4;

    // clamp OOB rows to a valid row: garbage only lands in unstored C rows
    int gr[4];
    #pragma unroll
    for (int i = 0; i < 4; i++) {
        int r = m0 + ar + 32 * i;
        gr[i] = (r < N_NODES) ? r : (N_NODES - 1);
    }

    auto stage = [&](int c, int buf) {
        const int k0 = c * 32;
        #pragma unroll
        for (int i = 0; i < 4; i++)
            cp_async16(smem_u32(&as[buf][ar + 32 * i][ac]),
                       &A[(size_t)gr[i] * F_IN + k0 + ac]);
        cp_async16(smem_u32(&ws[buf][wr][wc]),      &W[(size_t)(k0 + wr) * 64 + wc]);
        cp_async16(smem_u32(&ws[buf][wr + 16][wc]), &W[(size_t)(k0 + wr + 16) * 64 + wc]);
        asm volatile("cp.async.commit_group;");
    };

    float acc[8][4];
    #pragma unroll
    for (int j = 0; j < 8; j++)
        #pragma unroll
        for (int q = 0; q < 4; q++) acc[j][q] = 0.f;

    stage(0, 0);

    #pragma unroll
    for (int c = 0; c < N_CHUNKS; c++) {
        const int buf = c & 1;
        if (c + 1 < N_CHUNKS) {
            stage(c + 1, buf ^ 1);
            asm volatile("cp.async.wait_group 1;");
        } else {
            asm volatile("cp.async.wait_group 0;");
        }
        __syncthreads();

        #pragma unroll
        for (int kk = 0; kk < 32; kk += 8) {
            uint32_t a0 = as[buf][wrp * 16 + g][kk + tg];
            uint32_t a1 = as[buf][wrp * 16 + g + 8][kk + tg];
            uint32_t a2 = as[buf][wrp * 16 + g][kk + tg + 4];
            uint32_t a3 = as[buf][wrp * 16 + g + 8][kk + tg + 4];
            #pragma unroll
            for (int j = 0; j < 8; j++) {
                uint32_t b0 = ws[buf][kk + tg][8 * j + g];
                uint32_t b1 = ws[buf][kk + tg + 4][8 * j + g];
                mma_tf32(acc[j], a0, a1, a2, a3, b0, b1);
            }
        }
        __syncthreads();    // reads done before next-next stage overwrites buf
    }

    const int row0 = m0 + wrp * 16 + g;
    #pragma unroll
    for (int j = 0; j < 8; j++) {
        int col = 8 * j + 2 * tg;
        if (row0 < N_NODES)
            *(float2*)&C[(size_t)row0 * 64 + col] = make_float2(acc[j][0], acc[j][1]);
        if (row0 + 8 < N_NODES)
            *(float2*)&C[(size_t)(row0 + 8) * 64 + col] = make_float2(acc[j][2], acc[j][3]);
    }
}

// ---------------- warp-level 64-wide aggregation core -----------------------
__device__ __forceinline__ float4 agg_node(const float* __restrict__ h, int i,
                                           int h5 /*0 or 1*/, int l16) {
    const float di = d_dinv[i];
    const int n    = d_cnt[i];
    const int base = d_rowstart[i] - n;    // rowstart holds END after fill

    float4 acc = make_float4(0.f, 0.f, 0.f, 0.f);
    if (h5 == 0) {                    // self loop only on half 0
        float4 hv = *(const float4*)&h[(size_t)i * 64 + l16 * 4];
        float sl = di * di;
        acc.x = hv.x * sl; acc.y = hv.y * sl; acc.z = hv.z * sl; acc.w = hv.w * sl;
    }
    #pragma unroll 4
    for (int e = h5; e < n; e += 2) {
        int2 sn = d_csr[base + e];
        float nrm = __int_as_float(sn.y);
        float4 hv = *(const float4*)&h[(size_t)sn.x * 64 + l16 * 4];
        acc.x = fmaf(hv.x, nrm, acc.x);
        acc.y = fmaf(hv.y, nrm, acc.y);
        acc.z = fmaf(hv.z, nrm, acc.z);
        acc.w = fmaf(hv.w, nrm, acc.w);
    }
    acc.x += __shfl_xor_sync(0xFFFFFFFFu, acc.x, 16);
    acc.y += __shfl_xor_sync(0xFFFFFFFFu, acc.y, 16);
    acc.z += __shfl_xor_sync(0xFFFFFFFFu, acc.z, 16);
    acc.w += __shfl_xor_sync(0xFFFFFFFFu, acc.w, 16);
    return acc;
}

// ---------------- fused: agg(hbuf)+b1+relu -> @W2 -> hbuf2 -------------------
__global__ void k_agg_gemm(const float* __restrict__ hin,
                           const float* __restrict__ bias,
                           const float* __restrict__ W2,
                           float* __restrict__ hout) {
    __shared__ float as[64][65];      // 65-stride: conflict-free column reads
    __shared__ float ws[64][64];
    const int tid  = threadIdx.x;
    const int wid  = tid >> 5;
    const int lane = tid & 31;
    const int h5   = lane >> 4;
    const int l16  = lane & 15;
    const int m0   = blockIdx.x * 64;

    #pragma unroll
    for (int t = tid; t < 1024; t += 256) {
        int r  = t >> 4;
        int cc = (t & 15) * 4;
        *(float4*)&ws[r][cc] = *(const float4*)&W2[(size_t)r * 64 + cc];
    }

    float4 b4 = *(const float4*)&bias[l16 * 4];

    #pragma unroll
    for (int q = 0; q < 8; q++) {
        int local = wid * 8 + q;
        int i = m0 + local;
        float4 v = make_float4(0.f, 0.f, 0.f, 0.f);
        if (i < N_NODES) {
            float4 acc = agg_node(hin, i, h5, l16);
            v.x = fmaxf(acc.x + b4.x, 0.f);
            v.y = fmaxf(acc.y + b4.y, 0.f);
            v.z = fmaxf(acc.z + b4.z, 0.f);
            v.w = fmaxf(acc.w + b4.w, 0.f);
        }
        if (h5 == 0) {
            as[local][l16 * 4 + 0] = v.x;
            as[local][l16 * 4 + 1] = v.y;
            as[local][l16 * 4 + 2] = v.z;
            as[local][l16 * 4 + 3] = v.w;
        }
    }
    __syncthreads();

    const int tx = tid & 15;
    const int ty = tid >> 4;
    float acc[4][4] = {};
    #pragma unroll
    for (int kk = 0; kk < 64; kk++) {
        float a[4], b[4];
        #pragma unroll
        for (int i = 0; i < 4; i++) a[i] = as[ty + 16 * i][kk];
        #pragma unroll
        for (int j = 0; j < 4; j++) b[j] = ws[kk][tx + 16 * j];
        #pragma unroll
        for (int i = 0; i < 4; i++)
            #pragma unroll
            for (int j = 0; j < 4; j++)
                acc[i][j] = fmaf(a[i], b[j], acc[i][j]);
    }
    #pragma unroll
    for (int i = 0; i < 4; i++) {
        int gr = m0 + ty + 16 * i;
        if (gr < N_NODES) {
            #pragma unroll
            for (int j = 0; j < 4; j++)
                hout[(size_t)gr * 64 + tx + 16 * j] = acc[i][j];
        }
    }
}

// ---------------- fused: agg(hbuf2)+b2+relu -> @W3 -> h3 ---------------------
__global__ void k_agg_gemm3(const float* __restrict__ hin,
                            const float* __restrict__ bias,
                            const float* __restrict__ W3,
                            float* __restrict__ h3) {
    const int gwarp = (blockIdx.x * blockDim.x + threadIdx.x) >> 5;
    const int lane  = threadIdx.x & 31;
    if (gwarp >= N_NODES) return;
    const int i   = gwarp;
    const int h5  = lane >> 4;
    const int l16 = lane & 15;

    float w3v[4];
    #pragma unroll
    for (int j = 0; j < 4; j++)
        w3v[j] = __ldg(&W3[(l16 * 4 + j) * 2 + h5]);
    float4 b4 = *(const float4*)&bias[l16 * 4];

    float4 acc = agg_node(hin, i, h5, l16);
    float4 v;
    v.x = fmaxf(acc.x + b4.x, 0.f);
    v.y = fmaxf(acc.y + b4.y, 0.f);
    v.z = fmaxf(acc.z + b4.z, 0.f);
    v.w = fmaxf(acc.w + b4.w, 0.f);

    float p = v.x * w3v[0] + v.y * w3v[1] + v.z * w3v[2] + v.w * w3v[3];
    #pragma unroll
    for (int off = 8; off > 0; off >>= 1)
        p += __shfl_xor_sync(0xFFFFFFFFu, p, off);
    if (l16 == 0)
        h3[(size_t)i * 2 + h5] = p;
}

// ---------------- layer-3 aggregation + bias + log_softmax ------------------
__global__ void k_agg3(const float* __restrict__ h3, const float* __restrict__ b3,
                       float* __restrict__ out) {
    const int gwarp = (blockIdx.x * blockDim.x + threadIdx.x) >> 5;
    const int lane  = threadIdx.x & 31;
    if (gwarp >= N_NODES) return;
    const int i = gwarp;

    const float di = d_dinv[i];
    const int n    = d_cnt[i];
    const int base = d_rowstart[i] - n;

    float a0 = 0.f, a1 = 0.f;
    for (int e = lane; e < n; e += 32) {
        int2 sn = d_csr[base + e];
        float nrm = __int_as_float(sn.y);
        float2 hh = *(const float2*)&h3[(size_t)sn.x * 2];
        a0 = fmaf(hh.x, nrm, a0);
        a1 = fmaf(hh.y, nrm, a1);
    }
    #pragma unroll
    for (int off = 16; off > 0; off >>= 1) {
        a0 += __shfl_down_sync(0xFFFFFFFFu, a0, off);
        a1 += __shfl_down_sync(0xFFFFFFFFu, a1, off);
    }
    if (lane == 0) {
        a0 += h3[(size_t)i * 2 + 0] * (di * di) + b3[0];
        a1 += h3[(size_t)i * 2 + 1] * (di * di) + b3[1];
        float m = fmaxf(a0, a1);
        float lse = m + logf(expf(a0 - m) + expf(a1 - m));
        out[(size_t)i * 2 + 0] = a0 - lse;
        out[(size_t)i * 2 + 1] = a1 - lse;
    }
}

// ---------------- launch -----------------------------------------------------
extern "C" void kernel_launch(void* const* d_in, const int* in_sizes, int n_in,
                              void* d_out, int out_size) {
    const float* x  = (const float*)d_in[0];
    const int*   ei = (const int*)d_in[1];
    const float* W1 = (const float*)d_in[2];
    const float* b1 = (const float*)d_in[3];
    const float* W2 = (const float*)d_in[4];
    const float* b2 = (const float*)d_in[5];
    const float* W3 = (const float*)d_in[6];
    const float* b3 = (const float*)d_in[7];
    float* out = (float*)d_out;

    const int4* src4 = (const int4*)ei;
    const int4* dst4 = (const int4*)(ei + N_EDGES);

    void *p_cnt, *p_cur, *p_hbuf, *p_hbuf2, *p_h3;
    cudaGetSymbolAddress(&p_cnt, d_cnt);
    cudaGetSymbolAddress(&p_cur, d_cursor);
    cudaGetSymbolAddress(&p_hbuf, d_hbuf);
    cudaGetSymbolAddress(&p_hbuf2, d_hbuf2);
    cudaGetSymbolAddress(&p_h3, d_h3);

    const int NB_E4 = (N_EDGES / 4 + 255) / 256;
    const int NB_N  = (N_NODES + 255) / 256;
    const int NB_T  = (N_NODES + 127) / 128;
    const int NB_M  = (N_NODES + 63) / 64;
    const int NB_W  = (N_NODES * 32 + 255) / 256;

    // fork: gemm_tc (x,W1 only) runs concurrently with the CSR build
    cudaStream_t s2;
    cudaStreamCreateWithFlags(&s2, cudaStreamNonBlocking);
    cudaEvent_t evFork, evJoin;
    cudaEventCreateWithFlags(&evFork, cudaEventDisableTiming);
    cudaEventCreateWithFlags(&evJoin, cudaEventDisableTiming);

    cudaEventRecord(evFork, 0);
    cudaStreamWaitEvent(s2, evFork, 0);
    k_gemm_tc<<<NB_T, 256, 0, s2>>>(x, W1, (float*)p_hbuf);
    cudaEventRecord(evJoin, s2);

    // CSR build on the main (capture) stream
    cudaMemsetAsync(p_cnt, 0, N_NODES * sizeof(int));
    cudaMemsetAsync(p_cur, 0, sizeof(int));
    k_count<<<NB_E4, 256>>>(dst4);
    k_node<<<NB_N, 256>>>();
    k_fill<<<NB_E4, 256>>>(src4, dst4);

    // join: aggregation needs both CSR and hbuf
    cudaStreamWaitEvent(0, evJoin, 0);

    k_agg_gemm<<<NB_M, 256>>>((const float*)p_hbuf, b1, W2, (float*)p_hbuf2);
    k_agg_gemm3<<<NB_W, 256>>>((const float*)p_hbuf2, b2, W3, (float*)p_h3);
    k_agg3<<<NB_W, 256>>>((const float*)p_h3, b3, out);

    cudaEventDestroy(evFork);
    cudaEventDestroy(evJoin);
    cudaStreamDestroy(s2);
}